// round 4
// baseline (speedup 1.0000x reference)
#include <cuda_runtime.h>
#include <cstdint>
#include <math.h>

#define SEQ 512
#define NB  64
#define NH  1024
#define NG  4096

// ---------------- scratch (static device globals: allocation-free) ----------------
__device__ float g_xr [SEQ * NB * NH];   // x pre-rounded to tf32 (128 MB)
__device__ float g_wih[NG * NH];         // weight_ih pre-rounded (16 MB)
__device__ float g_whh[NG * NH];         // weight_hh pre-rounded (16 MB)
__device__ float g_h0[2][NB * NH];       // double-buffered layer0 h (tf32-rounded)
__device__ float g_h1[2][NB * NH];       // double-buffered layer1 h
__device__ float g_c0[NB * NH];
__device__ float g_c1[NB * NH];

__device__ __forceinline__ float tf32r(float x) {
    uint32_t u;
    asm("cvt.rna.tf32.f32 %0, %1;" : "=r"(u) : "f"(x));
    return __uint_as_float(u);
}

__global__ void k_round(const float* __restrict__ src, int which, int n) {
    float* dst = (which == 0) ? g_xr : (which == 1 ? g_wih : g_whh);
    int i = blockIdx.x * blockDim.x + threadIdx.x;
    int stride = gridDim.x * blockDim.x;
    for (; i < n; i += stride) dst[i] = tf32r(src[i]);
}

__global__ void k_init() {
    int i = blockIdx.x * blockDim.x + threadIdx.x;
    int stride = gridDim.x * blockDim.x;
    for (; i < NB * NH; i += stride) {
        g_h0[0][i] = 0.f; g_h0[1][i] = 0.f;
        g_h1[0][i] = 0.f; g_h1[1][i] = 0.f;
        g_c0[i] = 0.f;    g_c1[i] = 0.f;
    }
}

// ---------------------------------------------------------------------------------
// One "slot" fuses: layer0 @ time t0=s (rows 0-63) and layer1 @ time t1=s-1
// (rows 64-127) into a single M=128, N=4096, K=2048 TF32 GEMM + LSTM epilogue.
// Both halves multiply the SAME combined weight matrix [W_ih | W_hh].
// Each block owns 16 hidden units: gate cols {q*1024 + j0+jj} for q=0..3,
// i.e. a 128 x 64 gate tile, so the full i/f/g/o elementwise is in-block.
// ---------------------------------------------------------------------------------
__global__ __launch_bounds__(256) void k_slot(const float* __restrict__ bih,
                                              const float* __restrict__ bhh,
                                              float* __restrict__ out,
                                              int s, int wstates) {
    __shared__ float sm[128 * 68];        // 34.8 KB, reused: A|B tiles, then gates
    float* sA = sm;                       // [128][36]  (pad 36 => conflict-free frags)
    float* sB = sm + 128 * 36;            // [64][36]

    const int tid  = threadIdx.x;
    const int lane = tid & 31;
    const int wid  = tid >> 5;
    const int wm   = wid >> 1;            // warp row block (0..3) -> 32 rows
    const int wn   = wid & 1;             // warp col block (0..1) -> 32 cols
    const int j0   = blockIdx.x * 16;     // hidden-unit base for this block

    const int rp = s & 1, wq = rp ^ 1;
    const float* h0r = g_h0[rp];
    const float* h1r = g_h1[rp];
    float* h0w = g_h0[wq];
    float* h1w = g_h1[wq];

    const int  t0   = (s < SEQ) ? s : (SEQ - 1);   // clamp (results discarded at s=SEQ)
    const bool doL0 = (s < SEQ);
    const bool doL1 = (s > 0);
    const int  t1   = s - 1;

    float acc[2][4][4];
    #pragma unroll
    for (int a = 0; a < 2; a++)
        #pragma unroll
        for (int b = 0; b < 4; b++)
            #pragma unroll
            for (int c = 0; c < 4; c++) acc[a][b][c] = 0.f;

    float4 ra[4], rb[2];                  // register double-buffer for next K-chunk

    auto loadch = [&](int ch) {
        const int kc0 = ch * 32;
        #pragma unroll
        for (int i = 0; i < 4; i++) {
            int id = tid * 4 + i;         // 0..1023 float4s of A chunk
            int m  = id >> 3;
            int kg = kc0 + (id & 7) * 4;
            const float* p;
            if (m < 64)
                p = (kg < NH) ? (g_xr + ((size_t)t0 * NB + m) * NH + kg)
                              : (h0r + m * NH + (kg - NH));
            else
                p = (kg < NH) ? (h0r + (m - 64) * NH + kg)
                              : (h1r + (m - 64) * NH + (kg - NH));
            ra[i] = *(const float4*)p;
        }
        #pragma unroll
        for (int i = 0; i < 2; i++) {
            int id = tid * 2 + i;         // 0..511 float4s of B chunk
            int n  = id >> 3;
            int kg = kc0 + (id & 7) * 4;
            int grow = (n >> 4) * NH + j0 + (n & 15);   // gate row: q*1024 + j
            const float* p = (kg < NH) ? (g_wih + (size_t)grow * NH + kg)
                                       : (g_whh + (size_t)grow * NH + (kg - NH));
            rb[i] = *(const float4*)p;
        }
    };

    auto storech = [&]() {
        #pragma unroll
        for (int i = 0; i < 4; i++) {
            int id = tid * 4 + i;
            int m = id >> 3, k4 = id & 7;
            *(float4*)&sA[m * 36 + k4 * 4] = ra[i];
        }
        #pragma unroll
        for (int i = 0; i < 2; i++) {
            int id = tid * 2 + i;
            int n = id >> 3, k4 = id & 7;
            *(float4*)&sB[n * 36 + k4 * 4] = rb[i];
        }
    };

    const int g = lane >> 2, t = lane & 3;

    auto compute = [&]() {
        #pragma unroll
        for (int kk = 0; kk < 32; kk += 8) {
            uint32_t afr[2][4], bfr[4][2];
            #pragma unroll
            for (int mi = 0; mi < 2; mi++) {
                int r = wm * 32 + mi * 16 + g;
                afr[mi][0] = __float_as_uint(sA[r * 36 + kk + t]);
                afr[mi][1] = __float_as_uint(sA[(r + 8) * 36 + kk + t]);
                afr[mi][2] = __float_as_uint(sA[r * 36 + kk + t + 4]);
                afr[mi][3] = __float_as_uint(sA[(r + 8) * 36 + kk + t + 4]);
            }
            #pragma unroll
            for (int ni = 0; ni < 4; ni++) {
                int c = wn * 32 + ni * 8 + g;
                bfr[ni][0] = __float_as_uint(sB[c * 36 + kk + t]);
                bfr[ni][1] = __float_as_uint(sB[c * 36 + kk + t + 4]);
            }
            #pragma unroll
            for (int mi = 0; mi < 2; mi++)
                #pragma unroll
                for (int ni = 0; ni < 4; ni++) {
                    asm volatile(
                        "mma.sync.aligned.m16n8k8.row.col.f32.tf32.tf32.f32 "
                        "{%0,%1,%2,%3}, {%4,%5,%6,%7}, {%8,%9}, {%0,%1,%2,%3};\n"
                        : "+f"(acc[mi][ni][0]), "+f"(acc[mi][ni][1]),
                          "+f"(acc[mi][ni][2]), "+f"(acc[mi][ni][3])
                        : "r"(afr[mi][0]), "r"(afr[mi][1]),
                          "r"(afr[mi][2]), "r"(afr[mi][3]),
                          "r"(bfr[ni][0]), "r"(bfr[ni][1]));
                }
        }
    };

    loadch(0);
    for (int ch = 0; ch < 64; ++ch) {
        __syncthreads();
        storech();
        __syncthreads();
        if (ch < 63) loadch(ch + 1);      // overlap next global loads with MMA
        compute();
    }

    // ------- epilogue: exchange gates through smem, then fused LSTM update -------
    __syncthreads();
    float* sG = sm;                       // [128][68]
    #pragma unroll
    for (int mi = 0; mi < 2; mi++)
        #pragma unroll
        for (int ni = 0; ni < 4; ni++) {
            int r = wm * 32 + mi * 16 + g;
            int c = wn * 32 + ni * 8 + 2 * t;
            sG[r * 68 + c]           = acc[mi][ni][0];
            sG[r * 68 + c + 1]       = acc[mi][ni][1];
            sG[(r + 8) * 68 + c]     = acc[mi][ni][2];
            sG[(r + 8) * 68 + c + 1] = acc[mi][ni][3];
        }
    __syncthreads();

    for (int it = tid; it < 2048; it += 256) {
        int half = it >> 10;
        if (half == 0 && !doL0) continue;
        if (half == 1 && !doL1) continue;
        int rem = it & 1023;
        int b = rem >> 4, jj = rem & 15;
        int row = half * 64 + b;
        int j = j0 + jj;
        float gi = sG[row * 68 + jj]      + bih[j]          + bhh[j];
        float gf = sG[row * 68 + 16 + jj] + bih[NH + j]     + bhh[NH + j];
        float gg = sG[row * 68 + 32 + jj] + bih[2 * NH + j] + bhh[2 * NH + j];
        float go = sG[row * 68 + 48 + jj] + bih[3 * NH + j] + bhh[3 * NH + j];
        float iv = 1.f / (1.f + expf(-gi));
        float fv = 1.f / (1.f + expf(-gf));
        float gv = tanhf(gg);
        float ov = 1.f / (1.f + expf(-go));
        int idx = b * NH + j;
        if (half == 0) {
            float cn = fv * g_c0[idx] + iv * gv;
            g_c0[idx] = cn;
            float hn = ov * tanhf(cn);
            h0w[idx] = tf32r(hn);
            if (wstates && s == SEQ - 1) {
                out[(size_t)SEQ * NB * NH + idx] = hn;              // h_n[0]
                out[(size_t)SEQ * NB * NH + 2 * NB * NH + idx] = cn; // c_n[0]
            }
        } else {
            float cn = fv * g_c1[idx] + iv * gv;
            g_c1[idx] = cn;
            float hn = ov * tanhf(cn);
            h1w[idx] = tf32r(hn);
            out[((size_t)t1 * NB + b) * NH + j] = hn;               // outputs[t1]
            if (wstates && t1 == SEQ - 1) {
                out[(size_t)SEQ * NB * NH + NB * NH + idx] = hn;     // h_n[1]
                out[(size_t)SEQ * NB * NH + 3 * NB * NH + idx] = cn; // c_n[1]
            }
        }
    }
}

// ---------------------------------------------------------------------------------
extern "C" void kernel_launch(void* const* d_in, const int* in_sizes, int n_in,
                              void* d_out, int out_size) {
    const float* x   = (const float*)d_in[0];
    const float* wih = (const float*)d_in[1];
    const float* whh = (const float*)d_in[2];
    const float* bih = (const float*)d_in[3];
    const float* bhh = (const float*)d_in[4];
    float* out = (float*)d_out;

    const long long full = (long long)SEQ * NB * NH + 4LL * NB * NH;
    int wstates = ((long long)out_size >= full) ? 1 : 0;

    k_round<<<512, 256>>>(x, 0, SEQ * NB * NH);
    k_round<<<256, 256>>>(wih, 1, NG * NH);
    k_round<<<256, 256>>>(whh, 2, NG * NH);
    k_init<<<128, 256>>>();

    for (int s = 0; s <= SEQ; ++s)
        k_slot<<<64, 256>>>(bih, bhh, out, s, wstates);
}

// round 6
// speedup vs baseline: 1.3203x; 1.3203x over previous
#include <cuda_runtime.h>
#include <cstdint>
#include <math.h>

#define SEQ 512
#define NB  64
#define NH  1024
#define NG  4096

// ---------------- scratch (static device globals: allocation-free) ----------------
__device__ float g_xr [SEQ * NB * NH];   // x pre-rounded to tf32 (rna)
__device__ float g_wih[NG * NH];
__device__ float g_whh[NG * NH];
__device__ float g_bias[NG];             // bias_ih + bias_hh
__device__ float g_h0[2][NB * NH];       // double-buffered layer0 h (tf32-rounded)
__device__ float g_h1[2][NB * NH];
__device__ float g_c0[NB * NH];
__device__ float g_c1[NB * NH];

__device__ __forceinline__ float tf32r(float x) {
    uint32_t u;
    asm("cvt.rna.tf32.f32 %0, %1;" : "=r"(u) : "f"(x));
    return __uint_as_float(u);
}

__global__ void k_round(const float* __restrict__ src, int which, int n) {
    float* dst = (which == 0) ? g_xr : (which == 1 ? g_wih : g_whh);
    for (int i = blockIdx.x * blockDim.x + threadIdx.x; i < n; i += gridDim.x * blockDim.x)
        dst[i] = tf32r(src[i]);
}
__global__ void k_bias(const float* __restrict__ a, const float* __restrict__ b) {
    for (int i = blockIdx.x * blockDim.x + threadIdx.x; i < NG; i += gridDim.x * blockDim.x)
        g_bias[i] = a[i] + b[i];
}
__global__ void k_init() {
    for (int i = blockIdx.x * blockDim.x + threadIdx.x; i < NB * NH; i += gridDim.x * blockDim.x) {
        g_h0[0][i] = 0.f; g_h0[1][i] = 0.f;
        g_h1[0][i] = 0.f; g_h1[1][i] = 0.f;
        g_c0[i] = 0.f;    g_c1[i] = 0.f;
    }
}

// ---------------- PTX helpers (sm_80-level only: cp.async + mma.sync) ----------------
__device__ __forceinline__ uint32_t smem_u32(const void* p) {
    uint32_t r;
    asm("{ .reg .u64 t; cvta.to.shared.u64 t, %1; cvt.u32.u64 %0, t; }" : "=r"(r) : "l"(p));
    return r;
}
__device__ __forceinline__ void cp16(uint32_t dst, const void* src) {
    asm volatile("cp.async.cg.shared.global [%0], [%1], 16;\n" :: "r"(dst), "l"(src));
}
#define CP_COMMIT() asm volatile("cp.async.commit_group;\n" ::: "memory")
#define CP_WAIT(N)  asm volatile("cp.async.wait_group %0;\n" :: "n"(N) : "memory")

// SMEM geometry: K-chunk = 32 floats. Row stride 36 floats (144B): pad keeps
// fragment LDS conflict-free, rows stay 16B-contiguous for cp.async.
#define STAGES     6
#define A_WORDS    (128 * 36)            // 18432 B
#define B_WORDS    (64 * 36)             //  9216 B
#define STAGE_B    ((A_WORDS + B_WORDS) * 4)      // 27648 B
#define SMEM_BYTES (STAGES * STAGE_B)             // 165888 B

// ---------------------------------------------------------------------------------
// One "slot": M=128 (layer0@t0=s rows 0-63, layer1@t1=s-1 rows 64-127),
// N=4096 gates over 64 blocks (16 hidden units x 4 quadrants = 64 cols/block),
// K=2048 ([x|h0] rows 0-63, [h0|h1] rows 64-127), same B = [W_ih|W_hh] for both.
// 6-stage cp.async multistage pipeline, one __syncthreads per K-chunk,
// mma.sync.m16n8k8 tf32, warp grid 4(row) x 2(col) of 32x32 tiles.
// ---------------------------------------------------------------------------------
__global__ __launch_bounds__(256) void k_slot(float* __restrict__ out, int s, int wstates) {
    extern __shared__ float dyn[];

    const int tid  = threadIdx.x;
    const int lane = tid & 31;
    const int wid  = tid >> 5;
    const int wm   = wid >> 1;            // 0..3 -> 32-row band
    const int wn   = wid & 1;             // 0..1 -> 32-col band
    const int j0   = blockIdx.x * 16;

    const int rp = s & 1, wq = rp ^ 1;
    const float* h0r = g_h0[rp];
    const float* h1r = g_h1[rp];
    float* h0w = g_h0[wq];
    float* h1w = g_h1[wq];

    const int  t0   = (s < SEQ) ? s : (SEQ - 1);   // clamped; discarded at s=SEQ
    const bool doL0 = (s < SEQ);
    const bool doL1 = (s > 0);
    const int  t1   = s - 1;

    const uint32_t smem0 = smem_u32(dyn);

    // ---- chunk issuer: chunk c covers K columns [c*32, c*32+32) into stage st ----
    auto issue_chunk = [&](int c, int st) {
        const uint32_t aU = smem0 + (uint32_t)st * STAGE_B;
        const uint32_t bU = aU + A_WORDS * 4;
        const int  kb   = c * 32;
        const bool lowk = (c < 32);
        #pragma unroll
        for (int i = 0; i < 4; i++) {                 // A: 1024 float4s / 256 thr
            int id = i * 256 + tid;
            int m = id >> 3, q = id & 7;
            int kg = kb + q * 4;
            const float* src;
            if (m < 64)
                src = lowk ? (g_xr + ((size_t)t0 * NB + m) * NH + kg)
                           : (h0r + m * NH + (kg - NH));
            else
                src = lowk ? (h0r + (m - 64) * NH + kg)
                           : (h1r + (m - 64) * NH + (kg - NH));
            cp16(aU + (uint32_t)(m * 144 + q * 16), src);
        }
        const float* wb = lowk ? g_wih : g_whh;
        const int kk = kb & (NH - 1);
        #pragma unroll
        for (int i = 0; i < 2; i++) {                 // B: 512 float4s / 256 thr
            int id = i * 256 + tid;
            int n = id >> 3, q = id & 7;
            int grow = (n >> 4) * NH + j0 + (n & 15); // gate row: quad*NH + j
            cp16(bU + (uint32_t)(n * 144 + q * 16),
                 wb + (size_t)grow * NH + kk + q * 4);
        }
        CP_COMMIT();
    };

    float acc[2][4][4];
    #pragma unroll
    for (int a = 0; a < 2; a++)
        #pragma unroll
        for (int b = 0; b < 4; b++)
            #pragma unroll
            for (int c = 0; c < 4; c++) acc[a][b][c] = 0.f;

    const int g = lane >> 2, t = lane & 3;

    auto compute = [&](int st) {
        const float* sA = dyn + st * (STAGE_B / 4);
        const float* sB = sA + A_WORDS;
        #pragma unroll
        for (int kk = 0; kk < 32; kk += 8) {
            uint32_t afr[2][4], bfr[4][2];
            #pragma unroll
            for (int mi = 0; mi < 2; mi++) {
                int r = wm * 32 + mi * 16 + g;
                afr[mi][0] = __float_as_uint(sA[r * 36 + kk + t]);
                afr[mi][1] = __float_as_uint(sA[(r + 8) * 36 + kk + t]);
                afr[mi][2] = __float_as_uint(sA[r * 36 + kk + t + 4]);
                afr[mi][3] = __float_as_uint(sA[(r + 8) * 36 + kk + t + 4]);
            }
            #pragma unroll
            for (int ni = 0; ni < 4; ni++) {
                int c = wn * 32 + ni * 8 + g;
                bfr[ni][0] = __float_as_uint(sB[c * 36 + kk + t]);
                bfr[ni][1] = __float_as_uint(sB[c * 36 + kk + t + 4]);
            }
            #pragma unroll
            for (int mi = 0; mi < 2; mi++)
                #pragma unroll
                for (int ni = 0; ni < 4; ni++) {
                    asm volatile(
                        "mma.sync.aligned.m16n8k8.row.col.f32.tf32.tf32.f32 "
                        "{%0,%1,%2,%3}, {%4,%5,%6,%7}, {%8,%9}, {%0,%1,%2,%3};\n"
                        : "+f"(acc[mi][ni][0]), "+f"(acc[mi][ni][1]),
                          "+f"(acc[mi][ni][2]), "+f"(acc[mi][ni][3])
                        : "r"(afr[mi][0]), "r"(afr[mi][1]),
                          "r"(afr[mi][2]), "r"(afr[mi][3]),
                          "r"(bfr[ni][0]), "r"(bfr[ni][1]));
                }
        }
    };

    // ---- prologue: fill STAGES-1 = 5 stages ----
    #pragma unroll
    for (int c = 0; c < STAGES - 1; c++) issue_chunk(c, c);

    // ---- multistage mainloop: 64 chunks, one barrier each ----
    for (int c = 0; c < 64; ++c) {
        if      (c <= 59) CP_WAIT(4);     // chunk c's group complete
        else if (c == 60) CP_WAIT(3);
        else if (c == 61) CP_WAIT(2);
        else if (c == 62) CP_WAIT(1);
        else              CP_WAIT(0);
        __syncthreads();                  // data visible block-wide; stage (c-1)%6 free
        if (c + STAGES - 1 < 64)
            issue_chunk(c + STAGES - 1, (c + STAGES - 1) % STAGES);
        compute(c % STAGES);
    }

    // ------- epilogue: exchange gates through smem, then fused LSTM update -------
    __syncthreads();
    float* sG = dyn;                      // [128][68] = 34.8 KB, reuses stage 0/1
    #pragma unroll
    for (int mi = 0; mi < 2; mi++)
        #pragma unroll
        for (int ni = 0; ni < 4; ni++) {
            int r = wm * 32 + mi * 16 + g;
            int c = wn * 32 + ni * 8 + 2 * t;
            sG[r * 68 + c]           = acc[mi][ni][0];
            sG[r * 68 + c + 1]       = acc[mi][ni][1];
            sG[(r + 8) * 68 + c]     = acc[mi][ni][2];
            sG[(r + 8) * 68 + c + 1] = acc[mi][ni][3];
        }
    __syncthreads();

    for (int it = tid; it < 2048; it += 256) {
        int half = it >> 10;
        if (half == 0 && !doL0) continue;
        if (half == 1 && !doL1) continue;
        int rem = it & 1023;
        int b = rem >> 4, jj = rem & 15;
        int row = half * 64 + b;
        int j = j0 + jj;
        float gi = sG[row * 68 + jj]      + g_bias[j];
        float gf = sG[row * 68 + 16 + jj] + g_bias[NH + j];
        float gg = sG[row * 68 + 32 + jj] + g_bias[2 * NH + j];
        float go = sG[row * 68 + 48 + jj] + g_bias[3 * NH + j];
        float iv = 1.f / (1.f + expf(-gi));
        float fv = 1.f / (1.f + expf(-gf));
        float gv = tanhf(gg);
        float ov = 1.f / (1.f + expf(-go));
        int idx = b * NH + j;
        if (half == 0) {
            float cn = fv * g_c0[idx] + iv * gv;
            g_c0[idx] = cn;
            float hn = ov * tanhf(cn);
            h0w[idx] = tf32r(hn);
            if (wstates && s == SEQ - 1) {
                out[(size_t)SEQ * NB * NH + idx] = hn;               // h_n[0]
                out[(size_t)SEQ * NB * NH + 2 * NB * NH + idx] = cn; // c_n[0]
            }
        } else {
            float cn = fv * g_c1[idx] + iv * gv;
            g_c1[idx] = cn;
            float hn = ov * tanhf(cn);
            h1w[idx] = tf32r(hn);
            out[((size_t)t1 * NB + b) * NH + j] = hn;                // outputs[t1]
            if (wstates && t1 == SEQ - 1) {
                out[(size_t)SEQ * NB * NH + NB * NH + idx] = hn;     // h_n[1]
                out[(size_t)SEQ * NB * NH + 3 * NB * NH + idx] = cn; // c_n[1]
            }
        }
    }
}

// ---------------------------------------------------------------------------------
extern "C" void kernel_launch(void* const* d_in, const int* in_sizes, int n_in,
                              void* d_out, int out_size) {
    const float* x   = (const float*)d_in[0];
    const float* wih = (const float*)d_in[1];
    const float* whh = (const float*)d_in[2];
    const float* bih = (const float*)d_in[3];
    const float* bhh = (const float*)d_in[4];
    float* out = (float*)d_out;

    const long long full = (long long)SEQ * NB * NH + 4LL * NB * NH;
    int wstates = ((long long)out_size >= full) ? 1 : 0;

    static int smem_set = 0;
    if (!smem_set) {
        cudaFuncSetAttribute(k_slot, cudaFuncAttributeMaxDynamicSharedMemorySize, SMEM_BYTES);
        smem_set = 1;
    }

    k_round<<<512, 256>>>(x, 0, SEQ * NB * NH);
    k_round<<<256, 256>>>(wih, 1, NG * NH);
    k_round<<<256, 256>>>(whh, 2, NG * NH);
    k_bias<<<16, 256>>>(bih, bhh);
    k_init<<<128, 256>>>();

    for (int s = 0; s <= SEQ; ++s)
        k_slot<<<64, 256, SMEM_BYTES>>>(out, s, wstates);
}

// round 7
// speedup vs baseline: 3.3066x; 2.5044x over previous
#include <cuda_runtime.h>
#include <cuda_fp16.h>
#include <cstdint>
#include <math.h>

#define SEQ 512
#define NB  64
#define NH  1024
#define NG  4096

// ---------------- scratch (static device globals: allocation-free) ----------------
__device__ __half g_xh [SEQ * NB * NH];  // x in fp16 (64 MB)
__device__ __half g_wih[NG * NH];        // weights fp16 (8 MB each)
__device__ __half g_whh[NG * NH];
__device__ float  g_bias[NG];            // bias_ih + bias_hh (f32)
__device__ __half g_h0[2][NB * NH];      // double-buffered layer0 h (fp16)
__device__ __half g_h1[2][NB * NH];
__device__ float  g_c0[NB * NH];
__device__ float  g_c1[NB * NH];

__global__ void k_cvt(const float* __restrict__ src, int which, int n4) {
    __half* dst = (which == 0) ? g_xh : (which == 1 ? g_wih : g_whh);
    for (int i = blockIdx.x * blockDim.x + threadIdx.x; i < n4; i += gridDim.x * blockDim.x) {
        float4 v = ((const float4*)src)[i];
        __half2 lo = __floats2half2_rn(v.x, v.y);
        __half2 hi = __floats2half2_rn(v.z, v.w);
        ((__half2*)dst)[2 * i]     = lo;
        ((__half2*)dst)[2 * i + 1] = hi;
    }
}
__global__ void k_bias(const float* __restrict__ a, const float* __restrict__ b) {
    for (int i = blockIdx.x * blockDim.x + threadIdx.x; i < NG; i += gridDim.x * blockDim.x)
        g_bias[i] = a[i] + b[i];
}
__global__ void k_init() {
    const __half z = __float2half(0.f);
    for (int i = blockIdx.x * blockDim.x + threadIdx.x; i < NB * NH; i += gridDim.x * blockDim.x) {
        g_h0[0][i] = z; g_h0[1][i] = z;
        g_h1[0][i] = z; g_h1[1][i] = z;
        g_c0[i] = 0.f;  g_c1[i] = 0.f;
    }
}

// ---------------- PTX helpers (sm_80-level: cp.async + mma.sync) ----------------
__device__ __forceinline__ void cp16(uint32_t dst, const void* src) {
    asm volatile("cp.async.cg.shared.global [%0], [%1], 16;\n" :: "r"(dst), "l"(src));
}
#define CP_COMMIT() asm volatile("cp.async.commit_group;\n" ::: "memory")
#define CP_WAIT(N)  asm volatile("cp.async.wait_group %0;\n" :: "n"(N) : "memory")
__device__ __forceinline__ uint32_t smem_u32(const void* p) {
    uint32_t r;
    asm("{ .reg .u64 t; cvta.to.shared.u64 t, %1; cvt.u32.u64 %0, t; }" : "=r"(r) : "l"(p));
    return r;
}

// SMEM geometry: K-chunk = 64 fp16 (128B payload), row stride 144B (pad 16B:
// keeps cp.async 16B-aligned, spreads fragment-LDS banks).
#define STAGES     6
#define A_ROWB     144
#define A_BYTES    (128 * A_ROWB)                 // 18432
#define B_BYTES    (32 * A_ROWB)                  //  4608
#define STAGE_B    (A_BYTES + B_BYTES)            // 23040
#define SMEM_BYTES (STAGES * STAGE_B)             // 138240

// ---------------------------------------------------------------------------------
// One "slot": M=128 (layer0@t=s rows 0-63, layer1@t=s-1 rows 64-127),
// N=4096 gates over 128 blocks (8 hidden units x 4 quadrants = 32 cols/block),
// K=2048 ([x|h0] top, [h0|h1] bottom), shared B = [W_ih|W_hh] rows.
// fp16 m16n8k16 MMA, fp32 accum; 6-stage cp.async multistage, 32 K-chunks.
// ---------------------------------------------------------------------------------
__global__ __launch_bounds__(256) void k_slot(float* __restrict__ out, int s, int wstates) {
    extern __shared__ char dyn[];

    const int tid  = threadIdx.x;
    const int lane = tid & 31;
    const int wid  = tid >> 5;
    const int wm   = wid >> 1;            // 0..3 -> 32-row band
    const int wn   = wid & 1;             // 0..1 -> 16-col band
    const int j0   = blockIdx.x * 8;      // 8 hidden units per block

    const int rp = s & 1, wq = rp ^ 1;
    const __half* h0r = g_h0[rp];
    const __half* h1r = g_h1[rp];
    __half* h0w = g_h0[wq];
    __half* h1w = g_h1[wq];

    const int  t0   = (s < SEQ) ? s : (SEQ - 1);   // clamped; discarded at s=SEQ
    const bool doL0 = (s < SEQ);
    const bool doL1 = (s > 0);
    const int  t1   = s - 1;

    const uint32_t smem0 = smem_u32(dyn);

    // ---- chunk issuer: chunk c covers K columns [c*64, c*64+64) into stage st ----
    auto issue_chunk = [&](int c, int st) {
        const uint32_t aU = smem0 + (uint32_t)st * STAGE_B;
        const uint32_t bU = aU + A_BYTES;
        const int  kb   = c * 64;
        const bool lowk = (c < 16);
        #pragma unroll
        for (int i = 0; i < 4; i++) {                 // A: 1024 x 16B / 256 thr
            int id = i * 256 + tid;
            int m = id >> 3, q = id & 7;
            int kg = kb + q * 8;
            const __half* src;
            if (m < 64)
                src = lowk ? (g_xh + ((size_t)t0 * NB + m) * NH + kg)
                           : (h0r + m * NH + (kg - NH));
            else
                src = lowk ? (h0r + (m - 64) * NH + kg)
                           : (h1r + (m - 64) * NH + (kg - NH));
            cp16(aU + (uint32_t)(m * A_ROWB + q * 16), src);
        }
        const __half* wb = lowk ? g_wih : g_whh;
        const int kk = kb & (NH - 1);
        {                                             // B: 256 x 16B / 256 thr
            int n = tid >> 3, q = tid & 7;
            int grow = (n >> 3) * NH + j0 + (n & 7);  // gate row: quad*NH + unit
            cp16(bU + (uint32_t)(n * A_ROWB + q * 16),
                 wb + (size_t)grow * NH + kk + q * 8);
        }
        CP_COMMIT();
    };

    float acc[2][2][4];
    #pragma unroll
    for (int a = 0; a < 2; a++)
        #pragma unroll
        for (int b = 0; b < 2; b++)
            #pragma unroll
            for (int c = 0; c < 4; c++) acc[a][b][c] = 0.f;

    const int g = lane >> 2, t = lane & 3;

    auto compute = [&](int st) {
        const uint32_t* sA = (const uint32_t*)(dyn + st * STAGE_B);
        const uint32_t* sB = (const uint32_t*)(dyn + st * STAGE_B + A_BYTES);
        #pragma unroll
        for (int ks = 0; ks < 4; ks++) {              // 4 x k16 per 64-chunk
            const int ko = ks * 8 + t;                // 32-bit word offset in row
            uint32_t afr[2][4], bfr[2][2];
            #pragma unroll
            for (int mi = 0; mi < 2; mi++) {
                int r = wm * 32 + mi * 16 + g;
                afr[mi][0] = sA[r * 36 + ko];
                afr[mi][1] = sA[(r + 8) * 36 + ko];
                afr[mi][2] = sA[r * 36 + ko + 4];
                afr[mi][3] = sA[(r + 8) * 36 + ko + 4];
            }
            #pragma unroll
            for (int ni = 0; ni < 2; ni++) {
                int n = wn * 16 + ni * 8 + g;
                bfr[ni][0] = sB[n * 36 + ko];
                bfr[ni][1] = sB[n * 36 + ko + 4];
            }
            #pragma unroll
            for (int mi = 0; mi < 2; mi++)
                #pragma unroll
                for (int ni = 0; ni < 2; ni++) {
                    asm volatile(
                        "mma.sync.aligned.m16n8k16.row.col.f32.f16.f16.f32 "
                        "{%0,%1,%2,%3}, {%4,%5,%6,%7}, {%8,%9}, {%0,%1,%2,%3};\n"
                        : "+f"(acc[mi][ni][0]), "+f"(acc[mi][ni][1]),
                          "+f"(acc[mi][ni][2]), "+f"(acc[mi][ni][3])
                        : "r"(afr[mi][0]), "r"(afr[mi][1]),
                          "r"(afr[mi][2]), "r"(afr[mi][3]),
                          "r"(bfr[ni][0]), "r"(bfr[ni][1]));
                }
        }
    };

    // ---- prologue: fill STAGES-1 = 5 stages ----
    #pragma unroll
    for (int c = 0; c < STAGES - 1; c++) issue_chunk(c, c);

    // ---- multistage mainloop: 32 chunks, one barrier each ----
    for (int c = 0; c < 32; ++c) {
        if      (c <= 27) CP_WAIT(4);
        else if (c == 28) CP_WAIT(3);
        else if (c == 29) CP_WAIT(2);
        else if (c == 30) CP_WAIT(1);
        else              CP_WAIT(0);
        __syncthreads();
        if (c + STAGES - 1 < 32)
            issue_chunk(c + STAGES - 1, (c + STAGES - 1) % STAGES);
        compute(c % STAGES);
    }

    // ------- epilogue: exchange gates through smem, then fused LSTM update -------
    __syncthreads();
    float* sG = (float*)dyn;              // [128][36] = 18 KB
    #pragma unroll
    for (int mi = 0; mi < 2; mi++)
        #pragma unroll
        for (int ni = 0; ni < 2; ni++) {
            int r = wm * 32 + mi * 16 + g;
            int c = wn * 16 + ni * 8 + 2 * t;
            sG[r * 36 + c]           = acc[mi][ni][0];
            sG[r * 36 + c + 1]       = acc[mi][ni][1];
            sG[(r + 8) * 36 + c]     = acc[mi][ni][2];
            sG[(r + 8) * 36 + c + 1] = acc[mi][ni][3];
        }
    __syncthreads();

    // 256 threads, 128 rows: 2 threads/row, 4 consecutive units each.
    {
        const int row  = tid >> 1;
        const int half = row >> 6;
        const int b    = row & 63;
        const int jb   = (tid & 1) * 4;
        const bool act = (half == 0) ? doL0 : doL1;
        if (act) {
            float*  cst = half ? g_c1 : g_c0;
            __half* hwb = half ? h1w : h0w;
            const int idx = b * NH + j0 + jb;
            float4 cold = *(float4*)&cst[idx];
            float cv[4] = {cold.x, cold.y, cold.z, cold.w};
            float hv[4];
            #pragma unroll
            for (int u = 0; u < 4; u++) {
                int uu = jb + u;
                int j  = j0 + uu;
                float gi = sG[row * 36 + uu]      + g_bias[j];
                float gf = sG[row * 36 + 8 + uu]  + g_bias[NH + j];
                float gg = sG[row * 36 + 16 + uu] + g_bias[2 * NH + j];
                float go = sG[row * 36 + 24 + uu] + g_bias[3 * NH + j];
                float iv = 1.f / (1.f + expf(-gi));
                float fv = 1.f / (1.f + expf(-gf));
                float gv = tanhf(gg);
                float ov = 1.f / (1.f + expf(-go));
                float cn = fv * cv[u] + iv * gv;
                cv[u] = cn;
                hv[u] = ov * tanhf(cn);
            }
            *(float4*)&cst[idx] = make_float4(cv[0], cv[1], cv[2], cv[3]);
            *(__half2*)&hwb[idx]     = __floats2half2_rn(hv[0], hv[1]);
            *(__half2*)&hwb[idx + 2] = __floats2half2_rn(hv[2], hv[3]);
            if (half == 1) {
                *(float4*)&out[((size_t)t1 * NB + b) * NH + j0 + jb] =
                    make_float4(hv[0], hv[1], hv[2], hv[3]);
                if (wstates && t1 == SEQ - 1) {
                    #pragma unroll
                    for (int u = 0; u < 4; u++) {
                        out[(size_t)SEQ * NB * NH + NB * NH + idx + u]     = hv[u]; // h_n[1]
                        out[(size_t)SEQ * NB * NH + 3 * NB * NH + idx + u] = cv[u]; // c_n[1]
                    }
                }
            } else if (wstates && s == SEQ - 1) {
                #pragma unroll
                for (int u = 0; u < 4; u++) {
                    out[(size_t)SEQ * NB * NH + idx + u]               = hv[u];     // h_n[0]
                    out[(size_t)SEQ * NB * NH + 2 * NB * NH + idx + u] = cv[u];     // c_n[0]
                }
            }
        }
    }
}

// ---------------------------------------------------------------------------------
extern "C" void kernel_launch(void* const* d_in, const int* in_sizes, int n_in,
                              void* d_out, int out_size) {
    const float* x   = (const float*)d_in[0];
    const float* wih = (const float*)d_in[1];
    const float* whh = (const float*)d_in[2];
    const float* bih = (const float*)d_in[3];
    const float* bhh = (const float*)d_in[4];
    float* out = (float*)d_out;

    const long long full = (long long)SEQ * NB * NH + 4LL * NB * NH;
    int wstates = ((long long)out_size >= full) ? 1 : 0;

    static int smem_set = 0;
    if (!smem_set) {
        cudaFuncSetAttribute(k_slot, cudaFuncAttributeMaxDynamicSharedMemorySize, SMEM_BYTES);
        smem_set = 1;
    }

    k_cvt<<<512, 256>>>(x, 0, SEQ * NB * NH / 4);
    k_cvt<<<256, 256>>>(wih, 1, NG * NH / 4);
    k_cvt<<<256, 256>>>(whh, 2, NG * NH / 4);
    k_bias<<<16, 256>>>(bih, bhh);
    k_init<<<128, 256>>>();

    for (int s = 0; s <= SEQ; ++s)
        k_slot<<<128, 256, SMEM_BYTES>>>(out, s, wstates);
}

// round 8
// speedup vs baseline: 3.6291x; 1.0976x over previous
#include <cuda_runtime.h>
#include <cuda_fp16.h>
#include <cstdint>
#include <math.h>

#define SEQ 512
#define NB  64
#define NH  1024
#define NG  4096

// ---------------- scratch (static device globals: allocation-free) ----------------
__device__ __half g_xh [SEQ * NB * NH];  // x in fp16 (64 MB)
__device__ __half g_wih[NG * NH];        // weights fp16 (8 MB each)
__device__ __half g_whh[NG * NH];
__device__ float  g_bias[NG];            // bias_ih + bias_hh (f32)
__device__ __half g_h0[2][NB * NH];      // double-buffered layer0 h (fp16)
__device__ __half g_h1[2][NB * NH];
__device__ float  g_c0[NB * NH];
__device__ float  g_c1[NB * NH];
__device__ unsigned g_cnt;               // grid barrier arrival counter
__device__ volatile unsigned g_gen;      // grid barrier generation

__global__ void k_cvt(const float* __restrict__ src, int which, int n4) {
    __half* dst = (which == 0) ? g_xh : (which == 1 ? g_wih : g_whh);
    for (int i = blockIdx.x * blockDim.x + threadIdx.x; i < n4; i += gridDim.x * blockDim.x) {
        float4 v = ((const float4*)src)[i];
        ((__half2*)dst)[2 * i]     = __floats2half2_rn(v.x, v.y);
        ((__half2*)dst)[2 * i + 1] = __floats2half2_rn(v.z, v.w);
    }
}
__global__ void k_bias(const float* __restrict__ a, const float* __restrict__ b) {
    for (int i = blockIdx.x * blockDim.x + threadIdx.x; i < NG; i += gridDim.x * blockDim.x)
        g_bias[i] = a[i] + b[i];
}
__global__ void k_init() {
    int i0 = blockIdx.x * blockDim.x + threadIdx.x;
    if (i0 == 0) { g_cnt = 0u; g_gen = 0u; }
    const __half z = __float2half(0.f);
    for (int i = i0; i < NB * NH; i += gridDim.x * blockDim.x) {
        g_h0[0][i] = z; g_h0[1][i] = z;
        g_h1[0][i] = z; g_h1[1][i] = z;
        g_c0[i] = 0.f;  g_c1[i] = 0.f;
    }
}

// ---------------- PTX helpers ----------------
__device__ __forceinline__ void cp16(uint32_t dst, const void* src) {
    asm volatile("cp.async.cg.shared.global [%0], [%1], 16;\n" :: "r"(dst), "l"(src));
}
#define CP_COMMIT() asm volatile("cp.async.commit_group;\n" ::: "memory")
#define CP_WAIT(N)  asm volatile("cp.async.wait_group %0;\n" :: "n"(N) : "memory")
__device__ __forceinline__ uint32_t smem_u32(const void* p) {
    uint32_t r;
    asm("{ .reg .u64 t; cvta.to.shared.u64 t, %1; cvt.u32.u64 %0, t; }" : "=r"(r) : "l"(p));
    return r;
}
__device__ __forceinline__ void ldsm4(uint32_t& r0, uint32_t& r1, uint32_t& r2, uint32_t& r3,
                                      uint32_t addr) {
    asm volatile("ldmatrix.sync.aligned.m8n8.x4.shared.b16 {%0,%1,%2,%3}, [%4];"
                 : "=r"(r0), "=r"(r1), "=r"(r2), "=r"(r3) : "r"(addr));
}

// SMEM: A ring 4 stages x (128 rows x 144B) + resident B 32 chunks x (32 rows x 144B)
#define A_ROWB    144
#define A_STAGE_B (128 * A_ROWB)             // 18432
#define STAGES    4
#define B_OFF     (STAGES * A_STAGE_B)       // 73728
#define B_CHUNK_B (32 * A_ROWB)              // 4608
#define SMEM_TOT  (B_OFF + 32 * B_CHUNK_B)   // 221184

// ---------------------------------------------------------------------------------
// Persistent kernel. 128 blocks (one per SM, all co-resident), block owns 8 hidden
// units (32 gate cols). B slice = [W_ih|W_hh] rows resident in SMEM (144KB) loaded
// once. Per slot s: M=128 GEMM (layer0@t=s rows 0-63, layer1@t=s-1 rows 64-127),
// K=2048 streamed as 32 chunks through a 4-stage cp.async ring, fp16 m16n8k16 MMA
// with ldmatrix A-frags, fused LSTM epilogue, then a sense-counter grid barrier.
// ---------------------------------------------------------------------------------
__global__ __launch_bounds__(256) void k_lstm(float* __restrict__ out, int wstates) {
    extern __shared__ char dyn[];

    const int tid  = threadIdx.x;
    const int lane = tid & 31;
    const int wid  = tid >> 5;
    const int wm   = wid >> 1;            // 0..3 -> 32-row band
    const int wn   = wid & 1;             // 0..1 -> 16-col band
    const int j0   = blockIdx.x * 8;      // 8 hidden units per block

    const uint32_t smem0 = smem_u32(dyn);
    const uint32_t bRes  = smem0 + B_OFF;

    // ---- load resident B slice (once): chunk-major, same layout as frag reader ----
    {
        const int n = tid >> 3, q = tid & 7;                  // 256 x 16B per chunk
        const int grow = (n >> 3) * NH + j0 + (n & 7);        // gate row: quad*NH + unit
        for (int c = 0; c < 32; c++) {
            const __half* wb = (c < 16) ? g_wih : g_whh;
            const int kk = (c * 64) & (NH - 1);
            cp16(bRes + (uint32_t)(c * B_CHUNK_B + n * A_ROWB + q * 16),
                 wb + (size_t)grow * NH + kk + q * 8);
            CP_COMMIT();
        }
        CP_WAIT(0);
        __syncthreads();
    }

    const int g = lane >> 2, t = lane & 3;
    // ldmatrix lane addressing: lanes 0-15 -> rows +0..15 @ko, lanes 16-31 -> rows +0..15 @ko+4
    const int lrow = lane & 15;
    const int lhiw = (lane >> 4) * 4;

    for (int s = 0; s <= SEQ; ++s) {
        const int rp = s & 1, wq = rp ^ 1;
        const __half* h0r = g_h0[rp];
        const __half* h1r = g_h1[rp];
        __half* h0w = g_h0[wq];
        __half* h1w = g_h1[wq];
        const int  t0   = (s < SEQ) ? s : (SEQ - 1);
        const bool doL0 = (s < SEQ);
        const bool doL1 = (s > 0);
        const int  t1   = s - 1;

        // ---- A chunk issuer: K cols [c*64, c*64+64) into stage st ----
        auto issue_A = [&](int c, int st) {
            const uint32_t aU = smem0 + (uint32_t)st * A_STAGE_B;
            const int  kb   = c * 64;
            const bool lowk = (c < 16);
            #pragma unroll
            for (int i = 0; i < 4; i++) {                 // 1024 x 16B / 256 thr
                int id = i * 256 + tid;
                int m = id >> 3, q = id & 7;
                int kg = kb + q * 8;
                const __half* src;
                if (m < 64)
                    src = lowk ? (g_xh + ((size_t)t0 * NB + m) * NH + kg)
                               : (h0r + m * NH + (kg - NH));
                else
                    src = lowk ? (h0r + (m - 64) * NH + kg)
                               : (h1r + (m - 64) * NH + (kg - NH));
                cp16(aU + (uint32_t)(m * A_ROWB + q * 16), src);
            }
            CP_COMMIT();
        };

        float acc[2][2][4];
        #pragma unroll
        for (int a = 0; a < 2; a++)
            #pragma unroll
            for (int b = 0; b < 2; b++)
                #pragma unroll
                for (int c = 0; c < 4; c++) acc[a][b][c] = 0.f;

        issue_A(0, 0); issue_A(1, 1); issue_A(2, 2);      // prologue: 3 stages

        for (int c = 0; c < 32; ++c) {
            if      (c <= 29) CP_WAIT(2);
            else if (c == 30) CP_WAIT(1);
            else              CP_WAIT(0);
            __syncthreads();
            if (c + 3 < 32) issue_A(c + 3, (c + 3) & 3);

            const uint32_t aSt = smem0 + (uint32_t)(c & 3) * A_STAGE_B;
            const uint32_t* sB = (const uint32_t*)(dyn + B_OFF + c * B_CHUNK_B);
            #pragma unroll
            for (int ks = 0; ks < 4; ks++) {
                const int ko = ks * 8;
                uint32_t afr[2][4], bfr[2][2];
                #pragma unroll
                for (int mi = 0; mi < 2; mi++) {
                    int rbase = wm * 32 + mi * 16;
                    ldsm4(afr[mi][0], afr[mi][1], afr[mi][2], afr[mi][3],
                          aSt + (uint32_t)(((rbase + lrow) * 36 + ko + lhiw) * 4));
                }
                #pragma unroll
                for (int ni = 0; ni < 2; ni++) {
                    int n = wn * 16 + ni * 8 + g;
                    bfr[ni][0] = sB[n * 36 + ko + t];
                    bfr[ni][1] = sB[n * 36 + ko + t + 4];
                }
                #pragma unroll
                for (int mi = 0; mi < 2; mi++)
                    #pragma unroll
                    for (int ni = 0; ni < 2; ni++) {
                        asm volatile(
                            "mma.sync.aligned.m16n8k16.row.col.f32.f16.f16.f32 "
                            "{%0,%1,%2,%3}, {%4,%5,%6,%7}, {%8,%9}, {%0,%1,%2,%3};\n"
                            : "+f"(acc[mi][ni][0]), "+f"(acc[mi][ni][1]),
                              "+f"(acc[mi][ni][2]), "+f"(acc[mi][ni][3])
                            : "r"(afr[mi][0]), "r"(afr[mi][1]),
                              "r"(afr[mi][2]), "r"(afr[mi][3]),
                              "r"(bfr[ni][0]), "r"(bfr[ni][1]));
                    }
            }
        }

        // ------- epilogue: gate exchange via smem (reuses A stages), LSTM update -------
        __syncthreads();
        float* sG = (float*)dyn;          // [128][36]
        #pragma unroll
        for (int mi = 0; mi < 2; mi++)
            #pragma unroll
            for (int ni = 0; ni < 2; ni++) {
                int r = wm * 32 + mi * 16 + g;
                int cc = wn * 16 + ni * 8 + 2 * t;
                sG[r * 36 + cc]           = acc[mi][ni][0];
                sG[r * 36 + cc + 1]       = acc[mi][ni][1];
                sG[(r + 8) * 36 + cc]     = acc[mi][ni][2];
                sG[(r + 8) * 36 + cc + 1] = acc[mi][ni][3];
            }
        __syncthreads();

        {   // 2 threads per row, 4 consecutive units each
            const int row  = tid >> 1;
            const int half = row >> 6;
            const int b    = row & 63;
            const int jb   = (tid & 1) * 4;
            const bool act = (half == 0) ? doL0 : doL1;
            if (act) {
                float*  cst = half ? g_c1 : g_c0;
                __half* hwb = half ? h1w : h0w;
                const int idx = b * NH + j0 + jb;
                float4 cold = *(float4*)&cst[idx];
                float cv[4] = {cold.x, cold.y, cold.z, cold.w};
                float hv[4];
                #pragma unroll
                for (int u = 0; u < 4; u++) {
                    int uu = jb + u;
                    int j  = j0 + uu;
                    float gi = sG[row * 36 + uu]      + g_bias[j];
                    float gf = sG[row * 36 + 8 + uu]  + g_bias[NH + j];
                    float gg = sG[row * 36 + 16 + uu] + g_bias[2 * NH + j];
                    float go = sG[row * 36 + 24 + uu] + g_bias[3 * NH + j];
                    float iv = 1.f / (1.f + expf(-gi));
                    float fv = 1.f / (1.f + expf(-gf));
                    float gv = tanhf(gg);
                    float ov = 1.f / (1.f + expf(-go));
                    float cn = fv * cv[u] + iv * gv;
                    cv[u] = cn;
                    hv[u] = ov * tanhf(cn);
                }
                *(float4*)&cst[idx] = make_float4(cv[0], cv[1], cv[2], cv[3]);
                *(__half2*)&hwb[idx]     = __floats2half2_rn(hv[0], hv[1]);
                *(__half2*)&hwb[idx + 2] = __floats2half2_rn(hv[2], hv[3]);
                if (half == 1) {
                    *(float4*)&out[((size_t)t1 * NB + b) * NH + j0 + jb] =
                        make_float4(hv[0], hv[1], hv[2], hv[3]);
                    if (wstates && t1 == SEQ - 1) {
                        #pragma unroll
                        for (int u = 0; u < 4; u++) {
                            out[(size_t)SEQ * NB * NH + NB * NH + idx + u]     = hv[u];
                            out[(size_t)SEQ * NB * NH + 3 * NB * NH + idx + u] = cv[u];
                        }
                    }
                } else if (wstates && s == SEQ - 1) {
                    #pragma unroll
                    for (int u = 0; u < 4; u++) {
                        out[(size_t)SEQ * NB * NH + idx + u]               = hv[u];
                        out[(size_t)SEQ * NB * NH + 2 * NB * NH + idx + u] = cv[u];
                    }
                }
            }
        }

        // ------- grid barrier (sense counter); h writes released before next slot -------
        if (s < SEQ) {
            __syncthreads();
            if (tid == 0) {
                __threadfence();
                unsigned a = atomicAdd(&g_cnt, 1u);
                unsigned target = (unsigned)(s + 1);
                if (a == 127u) {
                    g_cnt = 0u;
                    __threadfence();
                    g_gen = target;
                } else {
                    while (g_gen < target) { }
                    __threadfence();
                }
            }
            __syncthreads();
        }
    }
}

// ---------------------------------------------------------------------------------
extern "C" void kernel_launch(void* const* d_in, const int* in_sizes, int n_in,
                              void* d_out, int out_size) {
    const float* x   = (const float*)d_in[0];
    const float* wih = (const float*)d_in[1];
    const float* whh = (const float*)d_in[2];
    const float* bih = (const float*)d_in[3];
    const float* bhh = (const float*)d_in[4];
    float* out = (float*)d_out;

    const long long full = (long long)SEQ * NB * NH + 4LL * NB * NH;
    int wstates = ((long long)out_size >= full) ? 1 : 0;

    static int smem_set = 0;
    if (!smem_set) {
        cudaFuncSetAttribute(k_lstm, cudaFuncAttributeMaxDynamicSharedMemorySize, SMEM_TOT);
        smem_set = 1;
    }

    k_cvt<<<512, 256>>>(x, 0, SEQ * NB * NH / 4);
    k_cvt<<<256, 256>>>(wih, 1, NG * NH / 4);
    k_cvt<<<256, 256>>>(whh, 2, NG * NH / 4);
    k_bias<<<16, 256>>>(bih, bhh);
    k_init<<<128, 256>>>();

    k_lstm<<<128, 256, SMEM_TOT>>>(out, wstates);
}